// round 14
// baseline (speedup 1.0000x reference)
#include <cuda_runtime.h>
#include <cuda_fp16.h>
#include <math.h>
#include <stdint.h>

// Problem shape (fixed)
#define Bn  16
#define TQv 2048
#define TKv 2048
#define Dv  1024

// ---------------------------------------------------------------------------
// Global fp16 hi/lo plane scratch (static __device__ => allowed)
// ---------------------------------------------------------------------------
#define N_ENC ((size_t)Bn * TKv * Dv)   // 33,554,432
#define N_DEC ((size_t)Bn * TQv * Dv)
#define N_W   ((size_t)Dv * Dv)
#define N_ALN ((size_t)Bn * TQv * TKv)  // 67,108,864

__device__ unsigned short g_enc_hi[N_ENC], g_enc_lo[N_ENC];
__device__ unsigned short g_dec_hi[N_DEC], g_dec_lo[N_DEC];
__device__ unsigned short g_w_hi[N_W],     g_w_lo[N_W];
__device__ unsigned short g_key_hi[N_ENC], g_key_lo[N_ENC];
__device__ unsigned short g_aln_hi[N_ALN];

// ---------------------------------------------------------------------------
// PTX helpers (baseline sm_80-level only: harness compiles for plain sm_103)
// ---------------------------------------------------------------------------
__device__ __forceinline__ uint32_t smem_u32(const void* p) {
    uint32_t a;
    asm("{ .reg .u64 t; cvta.to.shared.u64 t, %1; cvt.u32.u64 %0, t; }"
        : "=r"(a) : "l"(p));
    return a;
}

__device__ __forceinline__ void cp16(uint32_t s, const void* g) {
    asm volatile("cp.async.cg.shared.global [%0], [%1], 16;" :: "r"(s), "l"(g));
}
__device__ __forceinline__ void cp_commit() {
    asm volatile("cp.async.commit_group;");
}
template<int N>
__device__ __forceinline__ void cp_wait() {
    asm volatile("cp.async.wait_group %0;" :: "n"(N));
}

__device__ __forceinline__ uint4 ldsm4(uint32_t a) {
    uint4 r;
    asm volatile("ldmatrix.sync.aligned.m8n8.x4.shared.b16 {%0,%1,%2,%3}, [%4];"
                 : "=r"(r.x), "=r"(r.y), "=r"(r.z), "=r"(r.w) : "r"(a));
    return r;
}
__device__ __forceinline__ uint4 ldsm4t(uint32_t a) {
    uint4 r;
    asm volatile("ldmatrix.sync.aligned.m8n8.x4.trans.shared.b16 {%0,%1,%2,%3}, [%4];"
                 : "=r"(r.x), "=r"(r.y), "=r"(r.z), "=r"(r.w) : "r"(a));
    return r;
}

__device__ __forceinline__ void mma16816(float* c, const uint32_t* a, const uint32_t* b) {
    asm volatile(
        "mma.sync.aligned.m16n8k16.row.col.f32.f16.f16.f32 "
        "{%0,%1,%2,%3}, {%4,%5,%6,%7}, {%8,%9}, {%0,%1,%2,%3};"
        : "+f"(c[0]), "+f"(c[1]), "+f"(c[2]), "+f"(c[3])
        : "r"(a[0]), "r"(a[1]), "r"(a[2]), "r"(a[3]), "r"(b[0]), "r"(b[1]));
}

// Swizzled slot layouts (no padding, conflict-free for cp.async + ldmatrix):
//  A / B-NT slot: 128 rows x 64B (4 x 16B chunks):
//    off(r,c) = r*64 + ((c ^ ((r>>1)&3)) << 4)
//  B-NN slot: 32 k-rows x 256B (16 x 16B chunks):
//    off(k,nc) = k*256 + (((nc&8) | ((nc^k)&7)) << 4)
__device__ __forceinline__ int aswz(int r, int c) {
    return r * 64 + ((c ^ ((r >> 1) & 3)) << 4);
}
__device__ __forceinline__ int bswz(int k, int nc) {
    return k * 256 + (((nc & 8) | ((nc ^ k) & 7)) << 4);
}

// ---------------------------------------------------------------------------
// fp32 -> (hi, lo) fp16 split, vectorized
// ---------------------------------------------------------------------------
__global__ __launch_bounds__(256)
void split_k(const float4* __restrict__ x, __half2* __restrict__ hi,
             __half2* __restrict__ lo, int n4)
{
    int i = blockIdx.x * 256 + threadIdx.x;
    if (i >= n4) return;
    float4 v = x[i];
    __half hx = __float2half_rn(v.x), hy = __float2half_rn(v.y);
    __half hz = __float2half_rn(v.z), hw = __float2half_rn(v.w);
    __half lx = __float2half_rn(v.x - __half2float(hx));
    __half ly = __float2half_rn(v.y - __half2float(hy));
    __half lz = __float2half_rn(v.z - __half2float(hz));
    __half lw = __float2half_rn(v.w - __half2float(hw));
    hi[2 * i]     = __halves2half2(hx, hy);
    hi[2 * i + 1] = __halves2half2(hz, hw);
    lo[2 * i]     = __halves2half2(lx, ly);
    lo[2 * i + 1] = __halves2half2(lz, lw);
}

// ---------------------------------------------------------------------------
// fp16 multi-term mma.sync GEMM.  C[M,N] = A[M,K] @ op(B), hi/lo planes.
//   BT=true : B planes [N,K] K-contig (NT) -> ldmatrix non-trans
//   BT=false: B planes [K,N] N-contig (NN) -> ldmatrix trans
//   OUTP=true: epilogue writes hi/lo fp16 planes instead of fp32 C.
//   TERMS=3: ah*bh + ah*bl + al*bh ; TERMS=1: ah*bh
// Block 128x128, K-chunk 32, 8 warps (64x32 warp tiles).
// TERMS=3: 3-stage ring, hi-planes loaded first so lo-plane ldmatrix overlaps
//          the ah*bh MMA burst.
// TERMS=1: 4-stage ring with cross-barrier fragment double-buffering.
// ---------------------------------------------------------------------------
#define SLOTB 8192

template<bool BT, bool OUTP, int TERMS>
__global__ __launch_bounds__(256, 2)
void mma_gemm(const unsigned short* __restrict__ Ahi_g,
              const unsigned short* __restrict__ Alo_g,
              const unsigned short* __restrict__ Bhi_g,
              const unsigned short* __restrict__ Blo_g,
              float* __restrict__ Cg,
              unsigned short* __restrict__ Chi_g,
              unsigned short* __restrict__ Clo_g,
              int M, int N, int K,
              long long sA, long long sB, long long sC)
{
    constexpr int ASL    = (TERMS == 3) ? 2 : 1;     // A plane slots
    constexpr int BSL    = (TERMS >= 2) ? 2 : 1;     // B plane slots
    constexpr int STAGEB = (ASL + BSL) * SLOTB;
    constexpr int NSTG   = (TERMS == 1) ? 4 : 3;

    extern __shared__ char dsm[];
    const uint32_t sb0 = smem_u32(dsm);

    const unsigned short* Ahi = Ahi_g + (size_t)blockIdx.z * sA;
    const unsigned short* Alo = Alo_g + (size_t)blockIdx.z * sA;
    const unsigned short* Bhi = Bhi_g + (size_t)blockIdx.z * sB;
    const unsigned short* Blo = Blo_g + (size_t)blockIdx.z * sB;

    const int t = threadIdx.x;
    const int lane = t & 31, wid = t >> 5;
    const int wm = wid & 1, wn = wid >> 1;      // 2 x 4 warp grid -> 64x32 tiles
    const int m0 = blockIdx.y * 128, n0 = blockIdx.x * 128;

    const int ar  = t >> 2;            // A/B-NT row (0..63; +64)
    const int ac  = t & 3;             // 16B chunk within 64B row
    const int bkr = t >> 4;            // B-NN k-row (0..15; +16)
    const int bnc = t & 15;            // B-NN 16B chunk

    auto load_stage = [&](int s) {
        const uint32_t sb = sb0 + (uint32_t)(s % NSTG) * STAGEB;
        const int kt = s * 32;
        #pragma unroll
        for (int i = 0; i < 2; ++i) {
            int row = ar + 64 * i;
            size_t g = (size_t)(m0 + row) * K + kt + ac * 8;
            uint32_t sa = sb + (uint32_t)aswz(row, ac);
            cp16(sa, Ahi + g);
            if (TERMS == 3) cp16(sa + SLOTB, Alo + g);
        }
        if (BT) {
            #pragma unroll
            for (int i = 0; i < 2; ++i) {
                int row = ar + 64 * i;
                size_t g = (size_t)(n0 + row) * K + kt + ac * 8;
                uint32_t sa = sb + ASL * SLOTB + (uint32_t)aswz(row, ac);
                cp16(sa, Bhi + g);
                if (TERMS >= 2) cp16(sa + SLOTB, Blo + g);
            }
        } else {
            #pragma unroll
            for (int i = 0; i < 2; ++i) {
                int kr = bkr + 16 * i;
                size_t g = (size_t)(kt + kr) * N + n0 + bnc * 8;
                uint32_t sa = sb + ASL * SLOTB + (uint32_t)bswz(kr, bnc);
                cp16(sa, Bhi + g);
                if (TERMS >= 2) cp16(sa + SLOTB, Blo + g);
            }
        }
        cp_commit();
    };

    // ---- ldmatrix per-thread byte offsets (within a plane slot) ----
    int aoff[4][2];
    {
        int h = lane >> 4;                       // k8 selector (0/1)
        #pragma unroll
        for (int mi = 0; mi < 4; ++mi) {
            int row = wm * 64 + mi * 16 + (lane & 15);
            #pragma unroll
            for (int kk = 0; kk < 2; ++kk)
                aoff[mi][kk] = aswz(row, kk * 2 + h);
        }
    }
    int boff[2][2];
    {
        int j = lane >> 3, r = lane & 7;
        #pragma unroll
        for (int np = 0; np < 2; ++np) {
            #pragma unroll
            for (int kk = 0; kk < 2; ++kk) {
                if (BT) {
                    int n = wn * 32 + np * 16 + ((j >> 1) << 3) + r;
                    boff[np][kk] = aswz(n, kk * 2 + (j & 1));
                } else {
                    int k  = kk * 16 + ((j & 1) << 3) + r;
                    int nc = wn * 4 + np * 2 + (j >> 1);
                    boff[np][kk] = bswz(k, nc);
                }
            }
        }
    }

    auto frag_a = [&](uint32_t sb, int kk, int slot, uint32_t (&ah)[4][4]) {
        #pragma unroll
        for (int mi = 0; mi < 4; ++mi) {
            uint4 v = ldsm4(sb + (uint32_t)(slot * SLOTB) + (uint32_t)aoff[mi][kk]);
            ah[mi][0] = v.x; ah[mi][1] = v.y; ah[mi][2] = v.z; ah[mi][3] = v.w;
        }
    };
    auto frag_b = [&](uint32_t sb, int kk, int slot, uint32_t (&b)[4][2]) {
        #pragma unroll
        for (int np = 0; np < 2; ++np) {
            uint32_t a = sb + (uint32_t)(slot * SLOTB) + (uint32_t)boff[np][kk];
            uint4 v = BT ? ldsm4(a) : ldsm4t(a);
            b[2 * np][0] = v.x;     b[2 * np][1] = v.y;
            b[2 * np + 1][0] = v.z; b[2 * np + 1][1] = v.w;
        }
    };
    auto mma_set = [&](uint32_t (&a)[4][4], uint32_t (&b)[4][2],
                       float (&acc)[4][4][4]) {
        #pragma unroll
        for (int mi = 0; mi < 4; ++mi)
            #pragma unroll
            for (int ni = 0; ni < 4; ++ni)
                mma16816(acc[mi][ni], a[mi], b[ni]);
    };

    float acc[4][4][4];
    #pragma unroll
    for (int mi = 0; mi < 4; ++mi)
        #pragma unroll
        for (int ni = 0; ni < 4; ++ni)
            #pragma unroll
            for (int q = 0; q < 4; ++q) acc[mi][ni][q] = 0.0f;

    const int S = K >> 5;

    if constexpr (TERMS == 1) {
        // 4-stage ring, fragments double-buffered across the barrier.
        uint32_t ahF[4][4], bhF[4][2], ahG[4][4], bhG[4][2];
        load_stage(0);
        load_stage(1);
        load_stage(2);
        cp_wait<2>();               // group 0 done
        __syncthreads();            // stage 0 visible to all
        frag_a(sb0, 0, 0, ahF);
        frag_b(sb0, 0, ASL, bhF);

        for (int s = 0; s < S; ++s) {
            const uint32_t sb = sb0 + (uint32_t)(s % NSTG) * STAGEB;
            // Buffer (s+3)%4 = (s-1)%4: its last reads were before the barrier
            // inside iteration s-1, so overwriting now is safe.
            if (s + 3 < S) load_stage(s + 3); else cp_commit();
            frag_a(sb, 1, 0, ahG);
            frag_b(sb, 1, ASL, bhG);
            mma_set(ahF, bhF, acc);                     // (s, kk=0)
            if (s + 1 < S) {
                cp_wait<2>();                           // group s+1 done
                __syncthreads();                        // stage s+1 visible
                const uint32_t sbn = sb0 + (uint32_t)((s + 1) % NSTG) * STAGEB;
                frag_a(sbn, 0, 0, ahF);
                frag_b(sbn, 0, ASL, bhF);
            }
            mma_set(ahG, bhG, acc);                     // (s, kk=1)
        }
    } else {
        load_stage(0);
        load_stage(1);
        for (int s = 0; s < S; ++s) {
            cp_wait<1>();                              // group s complete
            __syncthreads();                           // stage s visible; buf (s+2)%3 free
            if (s + 2 < S) load_stage(s + 2); else cp_commit();

            const uint32_t sb = sb0 + (uint32_t)(s % 3) * STAGEB;
            #pragma unroll
            for (int kk = 0; kk < 2; ++kk) {
                uint32_t ah[4][4], al[4][4], bh[4][2], bl[4][2];
                // hi planes first, fire the hi*hi burst, then pull lo planes
                // underneath it.
                frag_a(sb, kk, 0, ah);
                frag_b(sb, kk, ASL, bh);
                mma_set(ah, bh, acc);
                frag_a(sb, kk, 1, al);
                frag_b(sb, kk, ASL + 1, bl);
                mma_set(ah, bl, acc);
                mma_set(al, bh, acc);
            }
        }
    }

    // ---- epilogue ----
    const int r0 = lane >> 2, c0 = (lane & 3) * 2;
    #pragma unroll
    for (int mi = 0; mi < 4; ++mi) {
        #pragma unroll
        for (int ni = 0; ni < 4; ++ni) {
            int row = m0 + wm * 64 + mi * 16 + r0;
            int col = n0 + wn * 32 + ni * 8 + c0;
            float* a = acc[mi][ni];
            if (OUTP) {
                #pragma unroll
                for (int h = 0; h < 2; ++h) {
                    size_t idx = (size_t)(row + 8 * h) * N + col;
                    float v0 = a[2 * h], v1 = a[2 * h + 1];
                    __half h0 = __float2half_rn(v0), h1 = __float2half_rn(v1);
                    __half l0 = __float2half_rn(v0 - __half2float(h0));
                    __half l1 = __float2half_rn(v1 - __half2float(h1));
                    *reinterpret_cast<__half2*>(Chi_g + (size_t)blockIdx.z * sC + idx)
                        = __halves2half2(h0, h1);
                    *reinterpret_cast<__half2*>(Clo_g + (size_t)blockIdx.z * sC + idx)
                        = __halves2half2(l0, l1);
                }
            } else {
                float* C = Cg + (size_t)blockIdx.z * sC;
                *reinterpret_cast<float2*>(&C[(size_t)row * N + col])
                    = make_float2(a[0], a[1]);
                *reinterpret_cast<float2*>(&C[(size_t)(row + 8) * N + col])
                    = make_float2(a[2], a[3]);
            }
        }
    }
}

// ---------------------------------------------------------------------------
// In-place row softmax (row length 2048); also emits fp16 hi plane.
// ---------------------------------------------------------------------------
__global__ __launch_bounds__(256)
void softmax2048(float* __restrict__ S, __half2* __restrict__ Phi)
{
    __shared__ float red_max[8];
    __shared__ float red_sum[8];

    float* p = S + (size_t)blockIdx.x * 2048;
    const int t = threadIdx.x;

    float4 a = reinterpret_cast<float4*>(p)[t];
    float4 b = reinterpret_cast<float4*>(p)[t + 256];

    float m = fmaxf(fmaxf(fmaxf(a.x, a.y), fmaxf(a.z, a.w)),
                    fmaxf(fmaxf(b.x, b.y), fmaxf(b.z, b.w)));
    #pragma unroll
    for (int o = 16; o; o >>= 1) m = fmaxf(m, __shfl_xor_sync(0xFFFFFFFFu, m, o));
    if ((t & 31) == 0) red_max[t >> 5] = m;
    __syncthreads();
    float mx = red_max[0];
    #pragma unroll
    for (int w = 1; w < 8; ++w) mx = fmaxf(mx, red_max[w]);

    a.x = __expf(a.x - mx); a.y = __expf(a.y - mx);
    a.z = __expf(a.z - mx); a.w = __expf(a.w - mx);
    b.x = __expf(b.x - mx); b.y = __expf(b.y - mx);
    b.z = __expf(b.z - mx); b.w = __expf(b.w - mx);

    float s = (a.x + a.y) + (a.z + a.w) + (b.x + b.y) + (b.z + b.w);
    #pragma unroll
    for (int o = 16; o; o >>= 1) s += __shfl_xor_sync(0xFFFFFFFFu, s, o);
    if ((t & 31) == 0) red_sum[t >> 5] = s;
    __syncthreads();
    float tot = red_sum[0];
    #pragma unroll
    for (int w = 1; w < 8; ++w) tot += red_sum[w];

    float inv = 1.0f / tot;
    a.x *= inv; a.y *= inv; a.z *= inv; a.w *= inv;
    b.x *= inv; b.y *= inv; b.z *= inv; b.w *= inv;

    reinterpret_cast<float4*>(p)[t]       = a;
    reinterpret_cast<float4*>(p)[t + 256] = b;

    size_t h2 = (size_t)blockIdx.x * 1024;   // half2 per row
    Phi[h2 + 2 * (size_t)t]           = __halves2half2(__float2half_rn(a.x), __float2half_rn(a.y));
    Phi[h2 + 2 * (size_t)t + 1]       = __halves2half2(__float2half_rn(a.z), __float2half_rn(a.w));
    Phi[h2 + 2 * (size_t)(t + 256)]     = __halves2half2(__float2half_rn(b.x), __float2half_rn(b.y));
    Phi[h2 + 2 * (size_t)(t + 256) + 1] = __halves2half2(__float2half_rn(b.z), __float2half_rn(b.w));
}

// ---------------------------------------------------------------------------
// launcher
// ---------------------------------------------------------------------------
extern "C" void kernel_launch(void* const* d_in, const int* in_sizes, int n_in,
                              void* d_out, int out_size)
{
    (void)in_sizes; (void)n_in; (void)out_size;
    const float* dec = (const float*)d_in[0];   // [B, TQ, D]
    const float* enc = (const float*)d_in[1];   // [B, TK, D]
    const float* W   = (const float*)d_in[2];   // [D, D]
    // wa_bias: zeros AND softmax-shift-invariant -> drops out of both outputs.

    float* ctx = (float*)d_out;                       // [B, TQ, D]
    float* aln = ctx + (size_t)Bn * TQv * Dv;         // [B, TQ, TK]

    unsigned short *enc_hi, *enc_lo, *dec_hi, *dec_lo, *w_hi, *w_lo;
    unsigned short *key_hi, *key_lo, *aln_hi;
    cudaGetSymbolAddress((void**)&enc_hi, g_enc_hi);
    cudaGetSymbolAddress((void**)&enc_lo, g_enc_lo);
    cudaGetSymbolAddress((void**)&dec_hi, g_dec_hi);
    cudaGetSymbolAddress((void**)&dec_lo, g_dec_lo);
    cudaGetSymbolAddress((void**)&w_hi,   g_w_hi);
    cudaGetSymbolAddress((void**)&w_lo,   g_w_lo);
    cudaGetSymbolAddress((void**)&key_hi, g_key_hi);
    cudaGetSymbolAddress((void**)&key_lo, g_key_lo);
    cudaGetSymbolAddress((void**)&aln_hi, g_aln_hi);

    constexpr int SMEM3 = 3 * 4 * SLOTB;   // 98304  (TERMS=3, 3 stages)
    constexpr int SMEM1 = 4 * 2 * SLOTB;   // 65536  (TERMS=1, 4 stages)
    cudaFuncSetAttribute((const void*)mma_gemm<false, true, 3>,
                         cudaFuncAttributeMaxDynamicSharedMemorySize, SMEM3);
    cudaFuncSetAttribute((const void*)mma_gemm<true, false, 3>,
                         cudaFuncAttributeMaxDynamicSharedMemorySize, SMEM3);
    cudaFuncSetAttribute((const void*)mma_gemm<false, false, 1>,
                         cudaFuncAttributeMaxDynamicSharedMemorySize, SMEM1);

    // 0) pre-split operands into fp16 hi/lo planes
    {
        int n4;
        n4 = (int)(N_ENC / 4);
        split_k<<<(n4 + 255) / 256, 256>>>((const float4*)enc, (__half2*)enc_hi,
                                           (__half2*)enc_lo, n4);
        n4 = (int)(N_DEC / 4);
        split_k<<<(n4 + 255) / 256, 256>>>((const float4*)dec, (__half2*)dec_hi,
                                           (__half2*)dec_lo, n4);
        n4 = (int)(N_W / 4);
        split_k<<<(n4 + 255) / 256, 256>>>((const float4*)W, (__half2*)w_hi,
                                           (__half2*)w_lo, n4);
    }

    // 1) keys = enc @ W  (NN: M=B*TK=32768, N=D, K=D), epilogue -> keys planes
    mma_gemm<false, true, 3><<<dim3(Dv / 128, (Bn * TKv) / 128, 1), 256, SMEM3>>>(
        enc_hi, enc_lo, w_hi, w_lo, nullptr, key_hi, key_lo,
        Bn * TKv, Dv, Dv, 0, 0, 0);

    // 2) score = dec @ keys^T (batched NT: M=TQ, N=TK, K=D) -> fp32 into aln
    mma_gemm<true, false, 3><<<dim3(TKv / 128, TQv / 128, Bn), 256, SMEM3>>>(
        dec_hi, dec_lo, key_hi, key_lo, aln, nullptr, nullptr,
        TQv, TKv, Dv,
        (long long)TQv * Dv, (long long)TKv * Dv, (long long)TQv * TKv);

    // 3) softmax over TK, in place; emits alignment fp16 hi plane
    softmax2048<<<Bn * TQv, 256>>>(aln, (__half2*)aln_hi);

    // 4) context = align @ enc (batched NN, 1-term: positive weights -> no
    //    cancellation; dropping enc_lo costs ~2.8e-4 rel) -> fp32 ctx
    mma_gemm<false, false, 1><<<dim3(Dv / 128, TQv / 128, Bn), 256, SMEM1>>>(
        aln_hi, aln_hi, enc_hi, enc_hi, ctx, nullptr, nullptr,
        TQv, Dv, TKv,
        (long long)TQv * TKv, (long long)TKv * Dv, (long long)TQv * Dv);
}

// round 15
// speedup vs baseline: 1.0384x; 1.0384x over previous
#include <cuda_runtime.h>
#include <cuda_fp16.h>
#include <math.h>
#include <stdint.h>

// Problem shape (fixed)
#define Bn  16
#define TQv 2048
#define TKv 2048
#define Dv  1024

// ---------------------------------------------------------------------------
// Global fp16 hi/lo plane scratch (static __device__ => allowed)
// ---------------------------------------------------------------------------
#define N_ENC ((size_t)Bn * TKv * Dv)   // 33,554,432
#define N_DEC ((size_t)Bn * TQv * Dv)
#define N_W   ((size_t)Dv * Dv)
#define N_ALN ((size_t)Bn * TQv * TKv)  // 67,108,864

__device__ unsigned short g_enc_hi[N_ENC], g_enc_lo[N_ENC];
__device__ unsigned short g_dec_hi[N_DEC], g_dec_lo[N_DEC];
__device__ unsigned short g_w_hi[N_W],     g_w_lo[N_W];
__device__ unsigned short g_key_hi[N_ENC], g_key_lo[N_ENC];
__device__ unsigned short g_aln_hi[N_ALN];

// ---------------------------------------------------------------------------
// PTX helpers (baseline sm_80-level only: harness compiles for plain sm_103)
// ---------------------------------------------------------------------------
__device__ __forceinline__ uint32_t smem_u32(const void* p) {
    uint32_t a;
    asm("{ .reg .u64 t; cvta.to.shared.u64 t, %1; cvt.u32.u64 %0, t; }"
        : "=r"(a) : "l"(p));
    return a;
}

__device__ __forceinline__ void cp16(uint32_t s, const void* g) {
    asm volatile("cp.async.cg.shared.global [%0], [%1], 16;" :: "r"(s), "l"(g));
}
__device__ __forceinline__ void cp_commit() {
    asm volatile("cp.async.commit_group;");
}
__device__ __forceinline__ void cp_wait1() {
    asm volatile("cp.async.wait_group 1;");
}

__device__ __forceinline__ uint4 ldsm4(uint32_t a) {
    uint4 r;
    asm volatile("ldmatrix.sync.aligned.m8n8.x4.shared.b16 {%0,%1,%2,%3}, [%4];"
                 : "=r"(r.x), "=r"(r.y), "=r"(r.z), "=r"(r.w) : "r"(a));
    return r;
}
__device__ __forceinline__ uint4 ldsm4t(uint32_t a) {
    uint4 r;
    asm volatile("ldmatrix.sync.aligned.m8n8.x4.trans.shared.b16 {%0,%1,%2,%3}, [%4];"
                 : "=r"(r.x), "=r"(r.y), "=r"(r.z), "=r"(r.w) : "r"(a));
    return r;
}

__device__ __forceinline__ void mma16816(float* c, const uint32_t* a, const uint32_t* b) {
    asm volatile(
        "mma.sync.aligned.m16n8k16.row.col.f32.f16.f16.f32 "
        "{%0,%1,%2,%3}, {%4,%5,%6,%7}, {%8,%9}, {%0,%1,%2,%3};"
        : "+f"(c[0]), "+f"(c[1]), "+f"(c[2]), "+f"(c[3])
        : "r"(a[0]), "r"(a[1]), "r"(a[2]), "r"(a[3]), "r"(b[0]), "r"(b[1]));
}

// Swizzled slot layouts (no padding, conflict-free for cp.async + ldmatrix):
//  A / B-NT slot: 128 rows x 64B (4 x 16B chunks):
//    off(r,c) = r*64 + ((c ^ ((r>>1)&3)) << 4)
//  B-NN slot: 32 k-rows x 256B (16 x 16B chunks):
//    off(k,nc) = k*256 + (((nc&8) | ((nc^k)&7)) << 4)
__device__ __forceinline__ int aswz(int r, int c) {
    return r * 64 + ((c ^ ((r >> 1) & 3)) << 4);
}
__device__ __forceinline__ int bswz(int k, int nc) {
    return k * 256 + (((nc & 8) | ((nc ^ k) & 7)) << 4);
}

// ---------------------------------------------------------------------------
// Fused fp32 -> (hi, lo) fp16 split for enc, dec, W in ONE launch.
// Grid covers the concatenated float4 ranges; per-thread range dispatch.
// ---------------------------------------------------------------------------
#define N4_ENC (int)(N_ENC / 4)
#define N4_DEC (int)(N_DEC / 4)
#define N4_W   (int)(N_W / 4)
#define N4_TOT (N4_ENC + N4_DEC + N4_W)

__global__ __launch_bounds__(256)
void split_all(const float4* __restrict__ enc, const float4* __restrict__ dec,
               const float4* __restrict__ w,
               __half2* __restrict__ enc_hi, __half2* __restrict__ enc_lo,
               __half2* __restrict__ dec_hi, __half2* __restrict__ dec_lo,
               __half2* __restrict__ w_hi,   __half2* __restrict__ w_lo)
{
    int i = blockIdx.x * 256 + threadIdx.x;
    const float4* x;
    __half2 *hi, *lo;
    if (i < N4_ENC) {
        x = enc; hi = enc_hi; lo = enc_lo;
    } else if (i < N4_ENC + N4_DEC) {
        i -= N4_ENC;
        x = dec; hi = dec_hi; lo = dec_lo;
    } else if (i < N4_TOT) {
        i -= N4_ENC + N4_DEC;
        x = w; hi = w_hi; lo = w_lo;
    } else {
        return;
    }
    float4 v = x[i];
    __half hx = __float2half_rn(v.x), hy = __float2half_rn(v.y);
    __half hz = __float2half_rn(v.z), hw = __float2half_rn(v.w);
    __half lx = __float2half_rn(v.x - __half2float(hx));
    __half ly = __float2half_rn(v.y - __half2float(hy));
    __half lz = __float2half_rn(v.z - __half2float(hz));
    __half lw = __float2half_rn(v.w - __half2float(hw));
    hi[2 * i]     = __halves2half2(hx, hy);
    hi[2 * i + 1] = __halves2half2(hz, hw);
    lo[2 * i]     = __halves2half2(lx, ly);
    lo[2 * i + 1] = __halves2half2(lz, lw);
}

// ---------------------------------------------------------------------------
// fp16 multi-term mma.sync GEMM.  C[M,N] = A[M,K] @ op(B), hi/lo planes.
//   BT=true : B planes [N,K] K-contig (NT) -> ldmatrix non-trans
//   BT=false: B planes [K,N] N-contig (NN) -> ldmatrix trans
//   OUTP=true: epilogue writes hi/lo fp16 planes instead of fp32 C.
//   TERMS=3: ah*bh + ah*bl + al*bh ; TERMS=1: ah*bh
// Block 128x128, K-chunk 32, 8 warps (64x32 warp tiles), 3-stage cp.async ring.
// TERMS==1 additionally uses cross-barrier fragment double-buffering.
// ---------------------------------------------------------------------------
#define SLOTB 8192

template<bool BT, bool OUTP, int TERMS>
__global__ __launch_bounds__(256, 2)
void mma_gemm(const unsigned short* __restrict__ Ahi_g,
              const unsigned short* __restrict__ Alo_g,
              const unsigned short* __restrict__ Bhi_g,
              const unsigned short* __restrict__ Blo_g,
              float* __restrict__ Cg,
              unsigned short* __restrict__ Chi_g,
              unsigned short* __restrict__ Clo_g,
              int M, int N, int K,
              long long sA, long long sB, long long sC)
{
    constexpr int ASL    = (TERMS == 3) ? 2 : 1;     // A plane slots
    constexpr int BSL    = (TERMS >= 2) ? 2 : 1;     // B plane slots
    constexpr int STAGEB = (ASL + BSL) * SLOTB;

    extern __shared__ char dsm[];
    const uint32_t sb0 = smem_u32(dsm);

    const unsigned short* Ahi = Ahi_g + (size_t)blockIdx.z * sA;
    const unsigned short* Alo = Alo_g + (size_t)blockIdx.z * sA;
    const unsigned short* Bhi = Bhi_g + (size_t)blockIdx.z * sB;
    const unsigned short* Blo = Blo_g + (size_t)blockIdx.z * sB;

    const int t = threadIdx.x;
    const int lane = t & 31, wid = t >> 5;
    const int wm = wid & 1, wn = wid >> 1;      // 2 x 4 warp grid -> 64x32 tiles
    const int m0 = blockIdx.y * 128, n0 = blockIdx.x * 128;

    const int ar  = t >> 2;            // A/B-NT row (0..63; +64)
    const int ac  = t & 3;             // 16B chunk within 64B row
    const int bkr = t >> 4;            // B-NN k-row (0..15; +16)
    const int bnc = t & 15;            // B-NN 16B chunk

    auto load_stage = [&](int s) {
        const uint32_t sb = sb0 + (uint32_t)(s % 3) * STAGEB;
        const int kt = s * 32;
        #pragma unroll
        for (int i = 0; i < 2; ++i) {
            int row = ar + 64 * i;
            size_t g = (size_t)(m0 + row) * K + kt + ac * 8;
            uint32_t sa = sb + (uint32_t)aswz(row, ac);
            cp16(sa, Ahi + g);
            if (TERMS == 3) cp16(sa + SLOTB, Alo + g);
        }
        if (BT) {
            #pragma unroll
            for (int i = 0; i < 2; ++i) {
                int row = ar + 64 * i;
                size_t g = (size_t)(n0 + row) * K + kt + ac * 8;
                uint32_t sa = sb + ASL * SLOTB + (uint32_t)aswz(row, ac);
                cp16(sa, Bhi + g);
                if (TERMS >= 2) cp16(sa + SLOTB, Blo + g);
            }
        } else {
            #pragma unroll
            for (int i = 0; i < 2; ++i) {
                int kr = bkr + 16 * i;
                size_t g = (size_t)(kt + kr) * N + n0 + bnc * 8;
                uint32_t sa = sb + ASL * SLOTB + (uint32_t)bswz(kr, bnc);
                cp16(sa, Bhi + g);
                if (TERMS >= 2) cp16(sa + SLOTB, Blo + g);
            }
        }
        cp_commit();
    };

    // ---- ldmatrix per-thread byte offsets (within a plane slot) ----
    int aoff[4][2];
    {
        int h = lane >> 4;                       // k8 selector (0/1)
        #pragma unroll
        for (int mi = 0; mi < 4; ++mi) {
            int row = wm * 64 + mi * 16 + (lane & 15);
            #pragma unroll
            for (int kk = 0; kk < 2; ++kk)
                aoff[mi][kk] = aswz(row, kk * 2 + h);
        }
    }
    int boff[2][2];
    {
        int j = lane >> 3, r = lane & 7;
        #pragma unroll
        for (int np = 0; np < 2; ++np) {
            #pragma unroll
            for (int kk = 0; kk < 2; ++kk) {
                if (BT) {
                    int n = wn * 32 + np * 16 + ((j >> 1) << 3) + r;
                    boff[np][kk] = aswz(n, kk * 2 + (j & 1));
                } else {
                    int k  = kk * 16 + ((j & 1) << 3) + r;
                    int nc = wn * 4 + np * 2 + (j >> 1);
                    boff[np][kk] = bswz(k, nc);
                }
            }
        }
    }

    auto frag_a = [&](uint32_t sb, int kk, int slot, uint32_t (&ah)[4][4]) {
        #pragma unroll
        for (int mi = 0; mi < 4; ++mi) {
            uint4 v = ldsm4(sb + (uint32_t)(slot * SLOTB) + (uint32_t)aoff[mi][kk]);
            ah[mi][0] = v.x; ah[mi][1] = v.y; ah[mi][2] = v.z; ah[mi][3] = v.w;
        }
    };
    auto frag_b = [&](uint32_t sb, int kk, int slot, uint32_t (&b)[4][2]) {
        #pragma unroll
        for (int np = 0; np < 2; ++np) {
            uint32_t a = sb + (uint32_t)(slot * SLOTB) + (uint32_t)boff[np][kk];
            uint4 v = BT ? ldsm4(a) : ldsm4t(a);
            b[2 * np][0] = v.x;     b[2 * np][1] = v.y;
            b[2 * np + 1][0] = v.z; b[2 * np + 1][1] = v.w;
        }
    };
    auto mma_set = [&](uint32_t (&a)[4][4], uint32_t (&b)[4][2],
                       float (&acc)[4][4][4]) {
        #pragma unroll
        for (int mi = 0; mi < 4; ++mi)
            #pragma unroll
            for (int ni = 0; ni < 4; ++ni)
                mma16816(acc[mi][ni], a[mi], b[ni]);
    };

    float acc[4][4][4];
    #pragma unroll
    for (int mi = 0; mi < 4; ++mi)
        #pragma unroll
        for (int ni = 0; ni < 4; ++ni)
            #pragma unroll
            for (int q = 0; q < 4; ++q) acc[mi][ni][q] = 0.0f;

    const int S = K >> 5;

    if constexpr (TERMS == 1) {
        // 3-stage ring, fragments double-buffered across the barrier (R12 form).
        uint32_t ahF[4][4], bhF[4][2], ahG[4][4], bhG[4][2];
        load_stage(0);
        load_stage(1);
        cp_wait1();                 // own group 0 done
        __syncthreads();            // stage 0 visible to all
        frag_a(sb0, 0, 0, ahF);
        frag_b(sb0, 0, ASL, bhF);

        for (int s = 0; s < S; ++s) {
            const uint32_t sb = sb0 + (uint32_t)(s % 3) * STAGEB;
            // Writing buffer (s+2)%3 is safe: last reads of it (stage s-1)
            // happened before the barrier inside iteration s-1.
            if (s + 2 < S) load_stage(s + 2); else cp_commit();
            frag_a(sb, 1, 0, ahG);
            frag_b(sb, 1, ASL, bhG);
            mma_set(ahF, bhF, acc);                     // (s, kk=0)
            if (s + 1 < S) {
                cp_wait1();                             // own group s+1 done
                __syncthreads();                        // stage s+1 visible
                const uint32_t sbn = sb0 + (uint32_t)((s + 1) % 3) * STAGEB;
                frag_a(sbn, 0, 0, ahF);
                frag_b(sbn, 0, ASL, bhF);
            }
            mma_set(ahG, bhG, acc);                     // (s, kk=1)
        }
    } else {
        load_stage(0);
        load_stage(1);
        for (int s = 0; s < S; ++s) {
            cp_wait1();                                // group s complete
            __syncthreads();                           // stage s visible; buf (s+2)%3 free
            if (s + 2 < S) load_stage(s + 2); else cp_commit();

            const uint32_t sb = sb0 + (uint32_t)(s % 3) * STAGEB;
            #pragma unroll
            for (int kk = 0; kk < 2; ++kk) {
                uint32_t ah[4][4], al[4][4], bh[4][2], bl[4][2];
                frag_a(sb, kk, 0, ah);
                if (TERMS == 3) {
                    #pragma unroll
                    for (int mi = 0; mi < 4; ++mi) {
                        uint4 w = ldsm4(sb + SLOTB + (uint32_t)aoff[mi][kk]);
                        al[mi][0] = w.x; al[mi][1] = w.y;
                        al[mi][2] = w.z; al[mi][3] = w.w;
                    }
                }
                frag_b(sb, kk, ASL, bh);
                frag_b(sb, kk, ASL + 1, bl);
                mma_set(ah, bh, acc);
                mma_set(ah, bl, acc);
                if (TERMS == 3) mma_set(al, bh, acc);
            }
        }
    }

    // ---- epilogue ----
    const int r0 = lane >> 2, c0 = (lane & 3) * 2;
    #pragma unroll
    for (int mi = 0; mi < 4; ++mi) {
        #pragma unroll
        for (int ni = 0; ni < 4; ++ni) {
            int row = m0 + wm * 64 + mi * 16 + r0;
            int col = n0 + wn * 32 + ni * 8 + c0;
            float* a = acc[mi][ni];
            if (OUTP) {
                #pragma unroll
                for (int h = 0; h < 2; ++h) {
                    size_t idx = (size_t)(row + 8 * h) * N + col;
                    float v0 = a[2 * h], v1 = a[2 * h + 1];
                    __half h0 = __float2half_rn(v0), h1 = __float2half_rn(v1);
                    __half l0 = __float2half_rn(v0 - __half2float(h0));
                    __half l1 = __float2half_rn(v1 - __half2float(h1));
                    *reinterpret_cast<__half2*>(Chi_g + (size_t)blockIdx.z * sC + idx)
                        = __halves2half2(h0, h1);
                    *reinterpret_cast<__half2*>(Clo_g + (size_t)blockIdx.z * sC + idx)
                        = __halves2half2(l0, l1);
                }
            } else {
                float* C = Cg + (size_t)blockIdx.z * sC;
                *reinterpret_cast<float2*>(&C[(size_t)row * N + col])
                    = make_float2(a[0], a[1]);
                *reinterpret_cast<float2*>(&C[(size_t)(row + 8) * N + col])
                    = make_float2(a[2], a[3]);
            }
        }
    }
}

// ---------------------------------------------------------------------------
// In-place row softmax (row length 2048); also emits fp16 hi plane.
// ---------------------------------------------------------------------------
__global__ __launch_bounds__(256)
void softmax2048(float* __restrict__ S, __half2* __restrict__ Phi)
{
    __shared__ float red_max[8];
    __shared__ float red_sum[8];

    float* p = S + (size_t)blockIdx.x * 2048;
    const int t = threadIdx.x;

    float4 a = reinterpret_cast<float4*>(p)[t];
    float4 b = reinterpret_cast<float4*>(p)[t + 256];

    float m = fmaxf(fmaxf(fmaxf(a.x, a.y), fmaxf(a.z, a.w)),
                    fmaxf(fmaxf(b.x, b.y), fmaxf(b.z, b.w)));
    #pragma unroll
    for (int o = 16; o; o >>= 1) m = fmaxf(m, __shfl_xor_sync(0xFFFFFFFFu, m, o));
    if ((t & 31) == 0) red_max[t >> 5] = m;
    __syncthreads();
    float mx = red_max[0];
    #pragma unroll
    for (int w = 1; w < 8; ++w) mx = fmaxf(mx, red_max[w]);

    a.x = __expf(a.x - mx); a.y = __expf(a.y - mx);
    a.z = __expf(a.z - mx); a.w = __expf(a.w - mx);
    b.x = __expf(b.x - mx); b.y = __expf(b.y - mx);
    b.z = __expf(b.z - mx); b.w = __expf(b.w - mx);

    float s = (a.x + a.y) + (a.z + a.w) + (b.x + b.y) + (b.z + b.w);
    #pragma unroll
    for (int o = 16; o; o >>= 1) s += __shfl_xor_sync(0xFFFFFFFFu, s, o);
    if ((t & 31) == 0) red_sum[t >> 5] = s;
    __syncthreads();
    float tot = red_sum[0];
    #pragma unroll
    for (int w = 1; w < 8; ++w) tot += red_sum[w];

    float inv = 1.0f / tot;
    a.x *= inv; a.y *= inv; a.z *= inv; a.w *= inv;
    b.x *= inv; b.y *= inv; b.z *= inv; b.w *= inv;

    reinterpret_cast<float4*>(p)[t]       = a;
    reinterpret_cast<float4*>(p)[t + 256] = b;

    size_t h2 = (size_t)blockIdx.x * 1024;   // half2 per row
    Phi[h2 + 2 * (size_t)t]           = __halves2half2(__float2half_rn(a.x), __float2half_rn(a.y));
    Phi[h2 + 2 * (size_t)t + 1]       = __halves2half2(__float2half_rn(a.z), __float2half_rn(a.w));
    Phi[h2 + 2 * (size_t)(t + 256)]     = __halves2half2(__float2half_rn(b.x), __float2half_rn(b.y));
    Phi[h2 + 2 * (size_t)(t + 256) + 1] = __halves2half2(__float2half_rn(b.z), __float2half_rn(b.w));
}

// ---------------------------------------------------------------------------
// launcher
// ---------------------------------------------------------------------------
extern "C" void kernel_launch(void* const* d_in, const int* in_sizes, int n_in,
                              void* d_out, int out_size)
{
    (void)in_sizes; (void)n_in; (void)out_size;
    const float* dec = (const float*)d_in[0];   // [B, TQ, D]
    const float* enc = (const float*)d_in[1];   // [B, TK, D]
    const float* W   = (const float*)d_in[2];   // [D, D]
    // wa_bias: zeros AND softmax-shift-invariant -> drops out of both outputs.

    float* ctx = (float*)d_out;                       // [B, TQ, D]
    float* aln = ctx + (size_t)Bn * TQv * Dv;         // [B, TQ, TK]

    unsigned short *enc_hi, *enc_lo, *dec_hi, *dec_lo, *w_hi, *w_lo;
    unsigned short *key_hi, *key_lo, *aln_hi;
    cudaGetSymbolAddress((void**)&enc_hi, g_enc_hi);
    cudaGetSymbolAddress((void**)&enc_lo, g_enc_lo);
    cudaGetSymbolAddress((void**)&dec_hi, g_dec_hi);
    cudaGetSymbolAddress((void**)&dec_lo, g_dec_lo);
    cudaGetSymbolAddress((void**)&w_hi,   g_w_hi);
    cudaGetSymbolAddress((void**)&w_lo,   g_w_lo);
    cudaGetSymbolAddress((void**)&key_hi, g_key_hi);
    cudaGetSymbolAddress((void**)&key_lo, g_key_lo);
    cudaGetSymbolAddress((void**)&aln_hi, g_aln_hi);

    constexpr int SMEM3 = 3 * 4 * SLOTB;   // 98304  (TERMS=3, 3 stages)
    constexpr int SMEM1 = 3 * 2 * SLOTB;   // 49152  (TERMS=1, 3 stages)
    cudaFuncSetAttribute((const void*)mma_gemm<false, true, 3>,
                         cudaFuncAttributeMaxDynamicSharedMemorySize, SMEM3);
    cudaFuncSetAttribute((const void*)mma_gemm<true, false, 3>,
                         cudaFuncAttributeMaxDynamicSharedMemorySize, SMEM3);
    cudaFuncSetAttribute((const void*)mma_gemm<false, false, 1>,
                         cudaFuncAttributeMaxDynamicSharedMemorySize, SMEM1);

    // 0) pre-split all operands into fp16 hi/lo planes (one launch)
    split_all<<<(N4_TOT + 255) / 256, 256>>>(
        (const float4*)enc, (const float4*)dec, (const float4*)W,
        (__half2*)enc_hi, (__half2*)enc_lo,
        (__half2*)dec_hi, (__half2*)dec_lo,
        (__half2*)w_hi,   (__half2*)w_lo);

    // 1) keys = enc @ W  (NN: M=B*TK=32768, N=D, K=D), epilogue -> keys planes
    mma_gemm<false, true, 3><<<dim3(Dv / 128, (Bn * TKv) / 128, 1), 256, SMEM3>>>(
        enc_hi, enc_lo, w_hi, w_lo, nullptr, key_hi, key_lo,
        Bn * TKv, Dv, Dv, 0, 0, 0);

    // 2) score = dec @ keys^T (batched NT: M=TQ, N=TK, K=D) -> fp32 into aln
    mma_gemm<true, false, 3><<<dim3(TKv / 128, TQv / 128, Bn), 256, SMEM3>>>(
        dec_hi, dec_lo, key_hi, key_lo, aln, nullptr, nullptr,
        TQv, TKv, Dv,
        (long long)TQv * Dv, (long long)TKv * Dv, (long long)TQv * TKv);

    // 3) softmax over TK, in place; emits alignment fp16 hi plane
    softmax2048<<<Bn * TQv, 256>>>(aln, (__half2*)aln_hi);

    // 4) context = align @ enc (batched NN, 1-term: positive weights -> no
    //    cancellation; dropping enc_lo costs ~2.8e-4 rel) -> fp32 ctx
    mma_gemm<false, false, 1><<<dim3(Dv / 128, TQv / 128, Bn), 256, SMEM1>>>(
        aln_hi, aln_hi, enc_hi, enc_hi, ctx, nullptr, nullptr,
        TQv, Dv, TKv,
        (long long)TQv * TKv, (long long)TKv * Dv, (long long)TQv * Dv);
}